// round 7
// baseline (speedup 1.0000x reference)
#include <cuda_runtime.h>

// QCNN closed form (see R0): layer k maps x_w <- prod_{j<=w} cos(x_j + theta_k_j),
// then out = sigmoid(x @ W + b).
//
// R7: R6's 2-lane shape (2048 warps, single wave) but kill the in-loop LDG
// latency: occupancy is NOT reg-limited (13.8 warps/SM -> up to ~128 regs free),
// so preload ALL parameters (30 theta + 20 W + 2 bias per lane) plus the 5
// inputs into registers up front with full MLP. The 6-layer loop is then pure
// FADD/MUFU/FMUL/SHFL. Epilogue reduced from 4 shuffles to 2.

#define NW 10
#define NLAYERS 6
#define FULLMASK 0xFFFFFFFFu

__global__ __launch_bounds__(256, 2) void qcnn_kernel(
    const float* __restrict__ inputs,   // (B, 10)
    const float* __restrict__ thetas,   // (6, 10)
    const float* __restrict__ W,        // (10, 4)
    const float* __restrict__ bias,     // (4,)
    float* __restrict__ out,            // (B, 4)
    int B)
{
    int tid = blockIdx.x * blockDim.x + threadIdx.x;
    int e = tid >> 1;          // element index
    int l = tid & 1;           // half: wires [5l, 5l+5)
    if (e >= B) return;        // warp-uniform (B*2 divisible by 256)

    int base = l * 5;

    // ---- Front-loaded register staging: every global read issues here. ----
    float th[NLAYERS * 5];
    #pragma unroll
    for (int k = 0; k < NLAYERS; k++)
        #pragma unroll
        for (int w = 0; w < 5; w++)
            th[k * 5 + w] = __ldg(thetas + k * NW + base + w);

    float wr[20];
    #pragma unroll
    for (int i = 0; i < 20; i++) wr[i] = __ldg(W + base * 4 + i);

    float b0 = __ldg(bias + 2 * l + 0);
    float b1 = __ldg(bias + 2 * l + 1);

    const float* row = inputs + (size_t)e * NW + base;
    float x0 = __ldg(row + 0);
    float x1 = __ldg(row + 1);
    float x2 = __ldg(row + 2);
    float x3 = __ldg(row + 3);
    float x4 = __ldg(row + 4);

    // ---- 6 layers: pure compute, no memory in the chain. ----
    #pragma unroll
    for (int k = 0; k < NLAYERS; k++) {
        float c0 = __cosf(x0 + th[k * 5 + 0]);
        float c1 = __cosf(x1 + th[k * 5 + 1]);
        float c2 = __cosf(x2 + th[k * 5 + 2]);
        float c3 = __cosf(x3 + th[k * 5 + 3]);
        float c4 = __cosf(x4 + th[k * 5 + 4]);

        // Local inclusive prefix products.
        float q1 = c0 * c1;
        float q2 = q1 * c2;
        float q3 = q2 * c3;
        float q4 = q3 * c4;

        // Exchange lane totals within the pair: one shuffle.
        float t = __shfl_xor_sync(FULLMASK, q4, 1, 2);
        float E = l ? t : 1.0f;

        x0 = E * c0;
        x1 = E * q1;
        x2 = E * q2;
        x3 = E * q3;
        x4 = E * q4;
    }

    // ---- Epilogue: partial dot over this half's 5 wires for all 4 outputs. ----
    float a0 = x0 * wr[0];
    float a1 = x0 * wr[1];
    float a2 = x0 * wr[2];
    float a3 = x0 * wr[3];
    a0 = fmaf(x1, wr[4],  a0);  a1 = fmaf(x1, wr[5],  a1);
    a2 = fmaf(x1, wr[6],  a2);  a3 = fmaf(x1, wr[7],  a3);
    a0 = fmaf(x2, wr[8],  a0);  a1 = fmaf(x2, wr[9],  a1);
    a2 = fmaf(x2, wr[10], a2);  a3 = fmaf(x2, wr[11], a3);
    a0 = fmaf(x3, wr[12], a0);  a1 = fmaf(x3, wr[13], a1);
    a2 = fmaf(x3, wr[14], a2);  a3 = fmaf(x3, wr[15], a3);
    a0 = fmaf(x4, wr[16], a0);  a1 = fmaf(x4, wr[17], a1);
    a2 = fmaf(x4, wr[18], a2);  a3 = fmaf(x4, wr[19], a3);

    // Cross-lane: each lane sends exactly what its peer needs (2 shuffles).
    // Lane 0 keeps outputs {0,1} (needs peer's a0,a1); lane 1 keeps {2,3}.
    float send0 = l ? a0 : a2;
    float send1 = l ? a1 : a3;
    float r0 = __shfl_xor_sync(FULLMASK, send0, 1, 2);  // peer's a0 (l=0) / a2 (l=1)
    float r1 = __shfl_xor_sync(FULLMASK, send1, 1, 2);  // peer's a1 (l=0) / a3 (l=1)

    float s0 = (l ? a2 : a0) + r0 + b0;
    float s1 = (l ? a3 : a1) + r1 + b1;

    float2 r;
    r.x = __frcp_rn(1.0f + __expf(-s0));
    r.y = __frcp_rn(1.0f + __expf(-s1));
    reinterpret_cast<float2*>(out)[e * 2 + l] = r;
}

extern "C" void kernel_launch(void* const* d_in, const int* in_sizes, int n_in,
                              void* d_out, int out_size) {
    const float* inputs = (const float*)d_in[0];  // (B, 10)
    const float* thetas = (const float*)d_in[1];  // (6, 10)
    const float* W      = (const float*)d_in[2];  // (10, 4)
    const float* bias   = (const float*)d_in[3];  // (4,)
    float* out = (float*)d_out;

    int B = in_sizes[0] / NW;        // 32768
    int nThreads = B * 2;            // 65536
    int threads = 256;
    int blocks = (nThreads + threads - 1) / threads;  // 256
    qcnn_kernel<<<blocks, threads>>>(inputs, thetas, W, bias, out, B);
}

// round 8
// speedup vs baseline: 1.1140x; 1.1140x over previous
#include <cuda_runtime.h>

// QCNN closed form (see R0): layer k maps x_w <- prod_{j<=w} cos(x_j + theta_k_j),
// then out = sigmoid(x @ W + b).
//
// R8: diagnosis — duration == 1.8MB of DRAM traffic / 245GB/s achieved BW.
// The kernel is DRAM-latency bound on the INPUT stream; R7 queued 52 parameter
// LDGs ahead of the 5 unique-DRAM input loads in the per-SM L1tex FIFO.
// Fix load ordering: inputs first (max early MLP), thetas second, W/bias
// deferred to the epilogue (L1 hits by then). Same 2-lane / 2048-warp shape.

#define NW 10
#define NLAYERS 6
#define FULLMASK 0xFFFFFFFFu

__global__ __launch_bounds__(256, 2) void qcnn_kernel(
    const float* __restrict__ inputs,   // (B, 10)
    const float* __restrict__ thetas,   // (6, 10)
    const float* __restrict__ W,        // (10, 4)
    const float* __restrict__ bias,     // (4,)
    float* __restrict__ out,            // (B, 4)
    int B)
{
    int tid = blockIdx.x * blockDim.x + threadIdx.x;
    int e = tid >> 1;          // element index
    int l = tid & 1;           // half: wires [5l, 5l+5)
    if (e >= B) return;        // warp-uniform (B*2 divisible by 256)

    int base = l * 5;

    // ---- 1) INPUT loads first: the only unique-DRAM traffic. 5 coalesced
    //         scalar LDGs per lane; a warp covers 640 contiguous bytes.
    const float* row = inputs + (size_t)e * NW + base;
    float x0 = __ldg(row + 0);
    float x1 = __ldg(row + 1);
    float x2 = __ldg(row + 2);
    float x3 = __ldg(row + 3);
    float x4 = __ldg(row + 4);

    // ---- 2) Theta loads second (broadcast; L2/L1 resident after first warp).
    float th[NLAYERS * 5];
    #pragma unroll
    for (int k = 0; k < NLAYERS; k++)
        #pragma unroll
        for (int w = 0; w < 5; w++)
            th[k * 5 + w] = __ldg(thetas + k * NW + base + w);

    // ---- 3) 6 layers: pure compute, no memory in the chain. ----
    #pragma unroll
    for (int k = 0; k < NLAYERS; k++) {
        float c0 = __cosf(x0 + th[k * 5 + 0]);
        float c1 = __cosf(x1 + th[k * 5 + 1]);
        float c2 = __cosf(x2 + th[k * 5 + 2]);
        float c3 = __cosf(x3 + th[k * 5 + 3]);
        float c4 = __cosf(x4 + th[k * 5 + 4]);

        // Local inclusive prefix products.
        float q1 = c0 * c1;
        float q2 = q1 * c2;
        float q3 = q2 * c3;
        float q4 = q3 * c4;

        // Exchange lane totals within the pair: one shuffle.
        float t = __shfl_xor_sync(FULLMASK, q4, 1, 2);
        float E = l ? t : 1.0f;

        x0 = E * c0;
        x1 = E * q1;
        x2 = E * q2;
        x3 = E * q3;
        x4 = E * q4;
    }

    // ---- 4) Epilogue: W/bias loads HERE (L1 hits, off the input window). ----
    const float* wp = W + base * 4;
    float a0 = x0 * __ldg(wp + 0);
    float a1 = x0 * __ldg(wp + 1);
    float a2 = x0 * __ldg(wp + 2);
    float a3 = x0 * __ldg(wp + 3);
    a0 = fmaf(x1, __ldg(wp + 4),  a0);  a1 = fmaf(x1, __ldg(wp + 5),  a1);
    a2 = fmaf(x1, __ldg(wp + 6),  a2);  a3 = fmaf(x1, __ldg(wp + 7),  a3);
    a0 = fmaf(x2, __ldg(wp + 8),  a0);  a1 = fmaf(x2, __ldg(wp + 9),  a1);
    a2 = fmaf(x2, __ldg(wp + 10), a2);  a3 = fmaf(x2, __ldg(wp + 11), a3);
    a0 = fmaf(x3, __ldg(wp + 12), a0);  a1 = fmaf(x3, __ldg(wp + 13), a1);
    a2 = fmaf(x3, __ldg(wp + 14), a2);  a3 = fmaf(x3, __ldg(wp + 15), a3);
    a0 = fmaf(x4, __ldg(wp + 16), a0);  a1 = fmaf(x4, __ldg(wp + 17), a1);
    a2 = fmaf(x4, __ldg(wp + 18), a2);  a3 = fmaf(x4, __ldg(wp + 19), a3);

    // Cross-lane: each lane sends exactly what its peer needs (2 shuffles).
    float send0 = l ? a0 : a2;
    float send1 = l ? a1 : a3;
    float r0 = __shfl_xor_sync(FULLMASK, send0, 1, 2);
    float r1 = __shfl_xor_sync(FULLMASK, send1, 1, 2);

    float s0 = (l ? a2 : a0) + r0 + __ldg(bias + 2 * l + 0);
    float s1 = (l ? a3 : a1) + r1 + __ldg(bias + 2 * l + 1);

    float2 r;
    r.x = __frcp_rn(1.0f + __expf(-s0));
    r.y = __frcp_rn(1.0f + __expf(-s1));
    reinterpret_cast<float2*>(out)[e * 2 + l] = r;
}

extern "C" void kernel_launch(void* const* d_in, const int* in_sizes, int n_in,
                              void* d_out, int out_size) {
    const float* inputs = (const float*)d_in[0];  // (B, 10)
    const float* thetas = (const float*)d_in[1];  // (6, 10)
    const float* W      = (const float*)d_in[2];  // (10, 4)
    const float* bias   = (const float*)d_in[3];  // (4,)
    float* out = (float*)d_out;

    int B = in_sizes[0] / NW;        // 32768
    int nThreads = B * 2;            // 65536
    int threads = 256;
    int blocks = (nThreads + threads - 1) / threads;  // 256
    qcnn_kernel<<<blocks, threads>>>(inputs, thetas, W, bias, out, B);
}